// round 1
// baseline (speedup 1.0000x reference)
#include <cuda_runtime.h>
#include <math.h>

#define T_STEPS 512
#define BATCH   512
#define IN_DIM  4
#define AUX_DIM 28
#define OUT_DIM 32
#define G_DIM   64
#define NROWS   1184      // 128 (W_i) + 1024 (W_r) + 32 (W_o)
#define NCTA    128
#define BS      4         // batch rows per CTA
#define NTHREADS 256
#define R_SM    704       // leading Wcat rows cached in smem

// ---------------- device globals (no allocation allowed) ----------------
__device__ float g_WcatT[G_DIM * NROWS];   // [g][row]
__device__ float g_bcat[NROWS];
__device__ float g_E[OUT_DIM * G_DIM];     // exp(W_s)        [o][g]
__device__ float g_sWr[G_DIM * OUT_DIM];   // sigmoid(W_rm.T) [g][o]
__device__ float g_partials[2][NCTA];
__device__ unsigned g_arrive;

__device__ __forceinline__ float sigm(float x) { return 1.0f / (1.0f + expf(-x)); }

__device__ __forceinline__ float wsum32(float v) {
#pragma unroll
    for (int s = 16; s > 0; s >>= 1) v += __shfl_xor_sync(0xffffffffu, v, s);
    return v;
}

// ---------------- prep: transpose/pack weights, reset sync state ----------------
__global__ void prep_kernel(const float* __restrict__ W_i, const float* __restrict__ b_i,
                            const float* __restrict__ W_r, const float* __restrict__ b_r,
                            const float* __restrict__ W_o, const float* __restrict__ b_o,
                            const float* __restrict__ W_s, const float* __restrict__ W_rm)
{
    int idx = blockIdx.x * blockDim.x + threadIdx.x;
    if (idx < G_DIM * NROWS) {
        int g = idx / NROWS, r = idx % NROWS;
        float v;
        if (r < 128)        v = W_i[r * G_DIM + g];
        else if (r < 1152)  v = W_r[(r - 128) * G_DIM + g];
        else                v = W_o[(r - 1152) * G_DIM + g];
        g_WcatT[idx] = v;
    }
    int i2 = idx - G_DIM * NROWS;
    if (i2 >= 0 && i2 < NROWS) {
        g_bcat[i2] = (i2 < 128) ? b_i[i2] : (i2 < 1152) ? b_r[i2 - 128] : b_o[i2 - 1152];
    }
    int i3 = i2 - NROWS;
    if (i3 >= 0 && i3 < OUT_DIM * G_DIM) g_E[i3] = expf(W_s[i3]);   // W_s is [o][g]
    int i4 = i3 - OUT_DIM * G_DIM;
    if (i4 >= 0 && i4 < G_DIM * OUT_DIM) {
        int g = i4 / OUT_DIM, o = i4 % OUT_DIM;
        g_sWr[i4] = 1.0f / (1.0f + expf(-W_rm[o * G_DIM + g]));
    }
    int i5 = i4 - G_DIM * OUT_DIM;
    if (i5 >= 0 && i5 < 2 * NCTA) ((float*)g_partials)[i5] = 0.0f;
    if (idx == 0) g_arrive = 0u;
}

// ---------------- main persistent kernel ----------------
// dynamic smem layout (floats):
#define OFF_WS    0
#define OFF_E     (OFF_WS + G_DIM * R_SM)         // 45056
#define OFF_SWR   (OFF_E + 2048)                  // 47104
#define OFF_FEAT  (OFF_SWR + 2048)                // 49152  [64][4]
#define OFF_GI    (OFF_FEAT + 256)                // 49408  [4][128]
#define OFF_RR    (OFF_GI + 512)                  // 49920  [4][1024]
#define OFF_OS    (OFF_RR + 4096)                 // 54016  [4][32]
#define OFF_CN    (OFF_OS + 128)                  // 54144  [4][32]
#define OFF_C     (OFF_CN + 128)                  // 54272  [4][32]
#define OFF_XM    (OFF_C + 128)                   // 54400  [4][4]
#define OFF_CR    (OFF_XM + 16)                   // 54416  [4][32]
#define OFF_CI    (OFF_CR + 128)                  // 54544  [4][4]
#define OFF_TH    (OFF_CI + 16)                   // 54560  [4][64]
#define OFF_B0    (OFF_TH + 256)                  // 54816  [32]
#define OFF_LNG   (OFF_B0 + 32)                   // 54848
#define OFF_LNB   (OFF_LNG + 32)                  // 54880
#define OFF_RED   (OFF_LNB + 32)                  // 54912  [128]
#define OFF_MISC  (OFF_RED + 128)                 // 55040  [8]
#define SMEM_FLOATS (OFF_MISC + 8)                // 55048
#define SMEM_BYTES  (SMEM_FLOATS * 4)             // 220192 B

__global__ void __launch_bounds__(NTHREADS, 1)
mclstm_kernel(const float* __restrict__ xm, const float* __restrict__ xa,
              const float* __restrict__ b0g, const float* __restrict__ ln_g,
              const float* __restrict__ ln_b, float* __restrict__ out)
{
    extern __shared__ float sm[];
    float* Ws     = sm + OFF_WS;
    float* E_s    = sm + OFF_E;
    float* sWr_s  = sm + OFF_SWR;
    float* feat4  = sm + OFF_FEAT;
    float* gi_s   = sm + OFF_GI;
    float* rr_s   = sm + OFF_RR;
    float* o_s    = sm + OFF_OS;
    float* cn_s   = sm + OFF_CN;
    float* c_s    = sm + OFF_C;
    float* xm_s   = sm + OFF_XM;
    float* coef_r = sm + OFF_CR;
    float* coef_i = sm + OFF_CI;
    float* th_s   = sm + OFF_TH;
    float* b0_s   = sm + OFF_B0;
    float* lng_s  = sm + OFF_LNG;
    float* lnb_s  = sm + OFF_LNB;
    float* red    = sm + OFF_RED;
    float* misc   = sm + OFF_MISC;

    const int tid = threadIdx.x;
    const int cta = blockIdx.x;
    const int bbase = cta * BS;
    const size_t OSTRIDE = (size_t)T_STEPS * BATCH * OUT_DIM;

    // one-time loads to smem
    for (int i = tid; i < G_DIM * R_SM; i += NTHREADS) {
        int g = i / R_SM, r = i % R_SM;
        Ws[i] = g_WcatT[g * NROWS + r];
    }
    for (int i = tid; i < OUT_DIM * G_DIM; i += NTHREADS) E_s[i] = g_E[i];
    for (int i = tid; i < G_DIM * OUT_DIM; i += NTHREADS) sWr_s[i] = g_sWr[i];
    if (tid < OUT_DIM) {
        b0_s[tid]  = b0g[tid];
        lng_s[tid] = ln_g[tid];
        lnb_s[tid] = ln_b[tid];
    }
    for (int i = tid; i < BS * OUT_DIM; i += NTHREADS) c_s[i] = 0.0f;
    __syncthreads();

    for (int t = 0; t < T_STEPS; ++t) {
        // ---- grid barrier: all CTAs must have published |c| partial for step t ----
        if (t > 0) {
            if (tid == 0) {
                unsigned target = (unsigned)NCTA * (unsigned)t;
                while (*((volatile unsigned*)&g_arrive) < target) { }
                __threadfence();
            }
            __syncthreads();
        }
        // ---- reduce partials -> global scalar S = sum(|c|) ----
        if (tid < NCTA) red[tid] = *((volatile float*)&g_partials[t & 1][tid]);
        __syncthreads();
        for (int s = 64; s > 0; s >>= 1) {
            if (tid < s) red[tid] += red[tid + s];
            __syncthreads();
        }
        const float invS = 1.0f / (red[0] + 1e-5f);

        // ---- build feat (g-major, [64][4]) + c_norm ----
        {
            int b = tid & 3, g = tid >> 2;
            int bg = bbase + b;
            float v;
            if (g < IN_DIM) {
                v = xm[((size_t)t * BATCH + bg) * IN_DIM + g];
                xm_s[b * 4 + g] = v;
            } else if (g < IN_DIM + AUX_DIM) {
                v = xa[((size_t)t * BATCH + bg) * AUX_DIM + (g - IN_DIM)];
            } else {
                float cv = c_s[b * OUT_DIM + (g - 32)];
                v = cv * invS;
                cn_s[b * OUT_DIM + (g - 32)] = v;
            }
            feat4[g * 4 + b] = v;
        }
        __syncthreads();

        // ---- MR gate first stage: ov0 = (cn - b0) @ exp(W_s), tanh ----
        {
            int b = tid & 3, g = tid >> 2;
            float a = 0.0f;
#pragma unroll
            for (int o = 0; o < OUT_DIM; ++o)
                a += (cn_s[b * 32 + o] - b0_s[o]) * E_s[o * 64 + g];
            th_s[b * 64 + g] = tanhf(a);
        }

        // ---- main fused GEMM: [4,64] @ WcatT -> 1184 preacts per b ----
        for (int rg = tid; rg < NROWS / 4; rg += NTHREADS) {
            int r0 = rg * 4;
            float acc[4][4];
#pragma unroll
            for (int b = 0; b < 4; ++b)
#pragma unroll
                for (int j = 0; j < 4; ++j) acc[b][j] = 0.0f;

            if (r0 < R_SM) {
#pragma unroll 8
                for (int g = 0; g < G_DIM; ++g) {
                    float4 f = *(const float4*)&feat4[g * 4];
                    float4 w = *(const float4*)&Ws[g * R_SM + r0];
                    acc[0][0] += f.x * w.x; acc[0][1] += f.x * w.y; acc[0][2] += f.x * w.z; acc[0][3] += f.x * w.w;
                    acc[1][0] += f.y * w.x; acc[1][1] += f.y * w.y; acc[1][2] += f.y * w.z; acc[1][3] += f.y * w.w;
                    acc[2][0] += f.z * w.x; acc[2][1] += f.z * w.y; acc[2][2] += f.z * w.z; acc[2][3] += f.z * w.w;
                    acc[3][0] += f.w * w.x; acc[3][1] += f.w * w.y; acc[3][2] += f.w * w.z; acc[3][3] += f.w * w.w;
                }
            } else {
#pragma unroll 8
                for (int g = 0; g < G_DIM; ++g) {
                    float4 f = *(const float4*)&feat4[g * 4];
                    float4 w = __ldg((const float4*)&g_WcatT[g * NROWS + r0]);
                    acc[0][0] += f.x * w.x; acc[0][1] += f.x * w.y; acc[0][2] += f.x * w.z; acc[0][3] += f.x * w.w;
                    acc[1][0] += f.y * w.x; acc[1][1] += f.y * w.y; acc[1][2] += f.y * w.z; acc[1][3] += f.y * w.w;
                    acc[2][0] += f.z * w.x; acc[2][1] += f.z * w.y; acc[2][2] += f.z * w.z; acc[2][3] += f.z * w.w;
                    acc[3][0] += f.w * w.x; acc[3][1] += f.w * w.y; acc[3][2] += f.w * w.z; acc[3][3] += f.w * w.w;
                }
            }
            float4 bb = __ldg((const float4*)&g_bcat[r0]);
            float bias[4] = { bb.x, bb.y, bb.z, bb.w };
            if (r0 < 128) {
#pragma unroll
                for (int b = 0; b < 4; ++b)
#pragma unroll
                    for (int j = 0; j < 4; ++j)
                        gi_s[b * 128 + r0 + j] = sigm(acc[b][j] + bias[j]);
            } else if (r0 < 1152) {
#pragma unroll
                for (int b = 0; b < 4; ++b)
#pragma unroll
                    for (int j = 0; j < 4; ++j)
                        rr_s[b * 1024 + (r0 - 128) + j] = fmaxf(acc[b][j] + bias[j], 0.0f);
            } else {
#pragma unroll
                for (int b = 0; b < 4; ++b)
#pragma unroll
                    for (int j = 0; j < 4; ++j)
                        o_s[b * 32 + (r0 - 1152) + j] = sigm(acc[b][j] + bias[j]);
            }
        }
        __syncthreads();

        // ---- L1-normalize coefficients ----
        if (tid < 128) {               // (b, n): redistribution rows
            int b = tid >> 5, n = tid & 31;
            float s = 0.0f;
#pragma unroll
            for (int p = 0; p < 32; p += 4) {
                float4 v = *(const float4*)&rr_s[b * 1024 + n * 32 + p];
                s += v.x + v.y + v.z + v.w;
            }
            coef_r[b * 32 + n] = c_s[b * 32 + n] / fmaxf(s, 1e-12f);
        } else if (tid < 144) {        // (b, ii): in-gate rows
            int q = tid - 128;
            int b = q >> 2, ii = q & 3;
            float s = 0.0f;
#pragma unroll
            for (int p = 0; p < 32; ++p) s += gi_s[b * 128 + ii * 32 + p];
            coef_i[b * 4 + ii] = xm_s[b * 4 + ii] / fmaxf(s, 1e-12f);
        }
        __syncthreads();

        // ---- m_new, ov1 + LayerNorm, MR gate, outputs, carry update ----
        if (tid < 128) {
            int b = tid >> 5, o = tid & 31;
            float m = 0.0f;
#pragma unroll
            for (int ii = 0; ii < 4; ++ii) m += coef_i[b * 4 + ii] * gi_s[b * 128 + ii * 32 + o];
#pragma unroll
            for (int n = 0; n < 32; ++n)  m += coef_r[b * 32 + n] * rr_s[b * 1024 + n * 32 + o];

            float pre = 0.0f;
#pragma unroll
            for (int g = 0; g < 64; ++g)  pre += th_s[b * 64 + g] * sWr_s[g * 32 + o];
            // LayerNorm over the 32 lanes of this warp (warp == b)
            float mu = wsum32(pre) * (1.0f / 32.0f);
            float d = pre - mu;
            float var = wsum32(d * d) * (1.0f / 32.0f);
            float ov1 = d * rsqrtf(var + 1e-5f) * lng_s[o] + lnb_s[o];

            float og = o_s[b * 32 + o];
            float f = 1.0f - og;
            float ov2 = ov1 - fmaxf(ov1 - f, 0.0f);
            float MR = fmaxf(ov2 + 1.0f - f, 0.0f) + f - 1.0f;
            float opr = og + MR;
            float h = og * m;
            float cnew = (1.0f - opr) * m;
            float mrf = MR * m;

            size_t base = ((size_t)t * BATCH + (bbase + b)) * OUT_DIM + o;
            out[base]               = h;
            out[OSTRIDE + base]     = cnew;
            out[2 * OSTRIDE + base] = og;
            out[3 * OSTRIDE + base] = MR;
            out[4 * OSTRIDE + base] = opr;
            out[5 * OSTRIDE + base] = mrf;
            out[6 * OSTRIDE + base] = h;

            c_s[b * 32 + o] = cnew;
            float a = wsum32(fabsf(cnew));
            if (o == 0) misc[b] = a;
        }
        __syncthreads();

        // ---- publish |c| partial for step t+1, arrive at grid barrier ----
        if (t < T_STEPS - 1) {
            if (tid == 0) {
                float part = misc[0] + misc[1] + misc[2] + misc[3];
                *((volatile float*)&g_partials[(t + 1) & 1][cta]) = part;
                __threadfence();
                atomicAdd(&g_arrive, 1u);
            }
        }
    }
}

// ---------------- launch ----------------
extern "C" void kernel_launch(void* const* d_in, const int* in_sizes, int n_in,
                              void* d_out, int out_size)
{
    const float* xm   = (const float*)d_in[0];
    const float* xa   = (const float*)d_in[1];
    const float* W_i  = (const float*)d_in[2];
    const float* b_i  = (const float*)d_in[3];
    const float* W_r  = (const float*)d_in[4];
    const float* b_r  = (const float*)d_in[5];
    const float* W_o  = (const float*)d_in[6];
    const float* b_o  = (const float*)d_in[7];
    const float* W_s  = (const float*)d_in[8];
    const float* W_rm = (const float*)d_in[9];
    const float* b0   = (const float*)d_in[10];
    const float* lng  = (const float*)d_in[11];
    const float* lnb  = (const float*)d_in[12];
    float* out = (float*)d_out;

    cudaFuncSetAttribute(mclstm_kernel, cudaFuncAttributeMaxDynamicSharedMemorySize, SMEM_BYTES);

    prep_kernel<<<320, 256>>>(W_i, b_i, W_r, b_r, W_o, b_o, W_s, W_rm);
    mclstm_kernel<<<NCTA, NTHREADS, SMEM_BYTES>>>(xm, xa, b0, lng, lnb, out);
}

// round 2
// speedup vs baseline: 1.3080x; 1.3080x over previous
#include <cuda_runtime.h>
#include <math.h>

#define T_STEPS 512
#define BATCH   512
#define IN_DIM  4
#define AUX_DIM 28
#define OUT_DIM 32
#define G_DIM   64
#define NROWS   1184      // 128 (W_i) + 1024 (W_r) + 32 (W_o)
#define NCTA    128
#define NTHREADS 256
#define R_SM    640       // Wcat rows cached in smem (warp-aligned boundary: thread 160)

typedef unsigned long long ull;

// ---------------- device globals ----------------
__device__ float g_WcatT[G_DIM * NROWS];   // [g][row]
__device__ float g_bcat[NROWS];
__device__ float g_E[OUT_DIM * G_DIM];     // exp(W_s)        [o][g]
__device__ float g_sWr[G_DIM * OUT_DIM];   // sigmoid(W_rm.T) [g][o]
__device__ float g_d0[G_DIM];              // b0 @ exp(W_s)   [g]
__device__ float g_partials[2][NCTA];
__device__ unsigned g_arrive;

__device__ __forceinline__ float sigm(float x) { return 1.0f / (1.0f + expf(-x)); }

__device__ __forceinline__ float wsum32(float v) {
#pragma unroll
    for (int s = 16; s > 0; s >>= 1) v += __shfl_xor_sync(0xffffffffu, v, s);
    return v;
}

__device__ __forceinline__ void ffma2(ull& d, ull a, ull b) {
    asm("fma.rn.f32x2 %0, %1, %2, %0;" : "+l"(d) : "l"(a), "l"(b));
}
__device__ __forceinline__ ull dup2(float x) {
    ull r; asm("mov.b64 %0, {%1, %1};" : "=l"(r) : "f"(x)); return r;
}
__device__ __forceinline__ float2 unp(ull v) {
    float2 r;
    r.x = __uint_as_float((unsigned)v);
    r.y = __uint_as_float((unsigned)(v >> 32));
    return r;
}

#define MM8(ACC, F01, F23, W) \
    ffma2(ACC[0], F01.x, W.x); ffma2(ACC[1], F01.x, W.y); \
    ffma2(ACC[2], F01.y, W.x); ffma2(ACC[3], F01.y, W.y); \
    ffma2(ACC[4], F23.x, W.x); ffma2(ACC[5], F23.x, W.y); \
    ffma2(ACC[6], F23.y, W.x); ffma2(ACC[7], F23.y, W.y);

// ---------------- prep: pack weights, derived constants, reset sync ----------------
__global__ void prep_kernel(const float* __restrict__ W_i, const float* __restrict__ b_i,
                            const float* __restrict__ W_r, const float* __restrict__ b_r,
                            const float* __restrict__ W_o, const float* __restrict__ b_o,
                            const float* __restrict__ W_s, const float* __restrict__ W_rm,
                            const float* __restrict__ b0)
{
    int idx = blockIdx.x * blockDim.x + threadIdx.x;
    if (idx < G_DIM * NROWS) {
        int g = idx / NROWS, r = idx % NROWS;
        float v;
        if (r < 128)        v = W_i[r * G_DIM + g];
        else if (r < 1152)  v = W_r[(r - 128) * G_DIM + g];
        else                v = W_o[(r - 1152) * G_DIM + g];
        g_WcatT[idx] = v;
    }
    int i2 = idx - G_DIM * NROWS;
    if (i2 >= 0 && i2 < NROWS)
        g_bcat[i2] = (i2 < 128) ? b_i[i2] : (i2 < 1152) ? b_r[i2 - 128] : b_o[i2 - 1152];
    int i3 = i2 - NROWS;
    if (i3 >= 0 && i3 < OUT_DIM * G_DIM) g_E[i3] = expf(W_s[i3]);
    int i4 = i3 - OUT_DIM * G_DIM;
    if (i4 >= 0 && i4 < G_DIM * OUT_DIM) {
        int g = i4 / OUT_DIM, o = i4 % OUT_DIM;
        g_sWr[i4] = 1.0f / (1.0f + expf(-W_rm[o * G_DIM + g]));
    }
    int i5 = i4 - G_DIM * OUT_DIM;
    if (i5 >= 0 && i5 < G_DIM) {
        float a = 0.0f;
        for (int o = 0; o < OUT_DIM; ++o) a += b0[o] * expf(W_s[o * G_DIM + i5]);
        g_d0[i5] = a;
    }
    int i6 = i5 - G_DIM;
    if (i6 >= 0 && i6 < 2 * NCTA) ((float*)g_partials)[i6] = 0.0f;
    if (idx == 0) g_arrive = 0u;
}

// ---------------- smem layout (float offsets) ----------------
#define OFF_WS    0                               // 40960
#define OFF_E     (OFF_WS + G_DIM * R_SM)         // 40960
#define OFF_SWR   (OFF_E + 2048)                  // 43008
#define OFF_BC    (OFF_SWR + 2048)                // 45056 (1184)
#define OFF_F1D   (OFF_BC + 1184)                 // 46240 (ull[32*4] = 256 f, 16B aligned)
#define OFF_CFD   (OFF_F1D + 256)                 // 46496 (ull[32*4])
#define OFF_GI    (OFF_CFD + 256)                 // 46752 [4][128]
#define OFF_RR    (OFF_GI + 512)                  // 47264 [4][1024]
#define OFF_OS    (OFF_RR + 4096)                 // 51360 [4][32]
#define OFF_C     (OFF_OS + 128)                  // 51488 [4][32]
#define OFF_XM    (OFF_C + 128)                   // 51616 [4][4]
#define OFF_CR    (OFF_XM + 16)                   // 51632 [4][32]
#define OFF_CI    (OFF_CR + 128)                  // 51760 [4][4]
#define OFF_TH    (OFF_CI + 16)                   // 51776 [4][64]
#define OFF_D0    (OFF_TH + 256)                  // 52032 [64]
#define OFF_OV1   (OFF_D0 + 64)                   // 52096 [4][32]
#define OFF_LNG   (OFF_OV1 + 128)                 // 52224
#define OFF_LNB   (OFF_LNG + 32)                  // 52256
#define OFF_MISC  (OFF_LNB + 32)                  // 52288 [8]; [0..3]=|c| row sums, [4]=S
#define SMEM_FLOATS (OFF_MISC + 8)
#define SMEM_BYTES  (SMEM_FLOATS * 4)             // ~209.2 KB

__global__ void __launch_bounds__(NTHREADS, 1)
mclstm_kernel(const float* __restrict__ xm, const float* __restrict__ xa,
              const float* __restrict__ ln_g, const float* __restrict__ ln_b,
              float* __restrict__ out)
{
    extern __shared__ float sm[];
    float* Ws     = sm + OFF_WS;
    float* E_s    = sm + OFF_E;
    float* sWr_s  = sm + OFF_SWR;
    float* bc_s   = sm + OFF_BC;
    ull*   f1d    = (ull*)(sm + OFF_F1D);
    ull*   cfd    = (ull*)(sm + OFF_CFD);
    float* gi_s   = sm + OFF_GI;
    float* rr_s   = sm + OFF_RR;
    float* o_s    = sm + OFF_OS;
    float* c_s    = sm + OFF_C;
    float* xm_s   = sm + OFF_XM;
    float* coef_r = sm + OFF_CR;
    float* coef_i = sm + OFF_CI;
    float* th_s   = sm + OFF_TH;
    float* d0_s   = sm + OFF_D0;
    float* ov1_s  = sm + OFF_OV1;
    float* lng_s  = sm + OFF_LNG;
    float* lnb_s  = sm + OFF_LNB;
    float* misc   = sm + OFF_MISC;

    const int tid = threadIdx.x;
    const int cta = blockIdx.x;
    const int bbase = cta * 4;
    const int bq = tid >> 6, gq = tid & 63;      // (batch, g) mapping for feat/qraw/tanh
    const size_t OSTRIDE = (size_t)T_STEPS * BATCH * OUT_DIM;

    // ---- prefetch t=0 inputs first (hide behind smem fills) ----
    float xcur = 0.0f;
    if (gq < IN_DIM)       xcur = xm[(size_t)(bbase + bq) * IN_DIM + gq];
    else if (gq < 32)      xcur = xa[(size_t)(bbase + bq) * AUX_DIM + (gq - IN_DIM)];

    // ---- one-time smem fills ----
    for (int i = tid; i < G_DIM * R_SM; i += NTHREADS) {
        int g = i / R_SM, r = i - g * R_SM;
        Ws[i] = g_WcatT[g * NROWS + r];
    }
    for (int i = tid; i < 2048; i += NTHREADS) { E_s[i] = g_E[i]; sWr_s[i] = g_sWr[i]; }
    for (int i = tid; i < NROWS; i += NTHREADS) bc_s[i] = g_bcat[i];
    if (tid < 64) d0_s[tid] = g_d0[tid];
    if (tid < 32) { lng_s[tid] = ln_g[tid]; lnb_s[tid] = ln_b[tid]; }
    if (tid < 128) { c_s[tid] = 0.0f; cfd[tid] = 0ull; }
    if (tid < 8) misc[tid] = 0.0f;
    __syncthreads();

    for (int t = 0; t < T_STEPS; ++t) {
        // ---- qraw = c @ E (local, pre-barrier), build feat-dup ----
        float q = 0.0f;
#pragma unroll
        for (int o = 0; o < OUT_DIM; ++o) q += c_s[bq * 32 + o] * E_s[o * 64 + gq];
        if (gq < 32) {
            f1d[gq * 4 + bq] = dup2(xcur);
            if (gq < IN_DIM) xm_s[bq * 4 + gq] = xcur;
        }
        __syncthreads();   // sync1: feat ready

        // ---- prefetch next step inputs (hidden under GEMM) ----
        float xnext = 0.0f;
        if (t + 1 < T_STEPS && gq < 32) {
            if (gq < IN_DIM) xnext = xm[((size_t)(t + 1) * BATCH + bbase + bq) * IN_DIM + gq];
            else             xnext = xa[((size_t)(t + 1) * BATCH + bbase + bq) * AUX_DIM + (gq - IN_DIM)];
        }

        // ---- GEMM: both halves, raw c (no invS yet) ----
        ull a1[2][8], a2[2][8];
#pragma unroll
        for (int it = 0; it < 2; ++it) {
            if (it == 1 && tid >= 40) break;
#pragma unroll
            for (int k = 0; k < 8; ++k) { a1[it][k] = 0ull; a2[it][k] = 0ull; }
            const int r0 = (tid + it * NTHREADS) * 4;
            ull* p1 = a1[it];
            ull* p2 = a2[it];
            if (it == 0 && tid < (R_SM / 4)) {
#pragma unroll 8
                for (int g = 0; g < 32; ++g) {
                    ulonglong2 f01 = *(const ulonglong2*)(f1d + g * 4);
                    ulonglong2 f23 = *(const ulonglong2*)(f1d + g * 4 + 2);
                    ulonglong2 w1  = *(const ulonglong2*)(Ws + g * R_SM + r0);
                    MM8(p1, f01, f23, w1);
                    ulonglong2 c01 = *(const ulonglong2*)(cfd + g * 4);
                    ulonglong2 c23 = *(const ulonglong2*)(cfd + g * 4 + 2);
                    ulonglong2 w2  = *(const ulonglong2*)(Ws + (32 + g) * R_SM + r0);
                    MM8(p2, c01, c23, w2);
                }
            } else {
#pragma unroll 8
                for (int g = 0; g < 32; ++g) {
                    ulonglong2 f01 = *(const ulonglong2*)(f1d + g * 4);
                    ulonglong2 f23 = *(const ulonglong2*)(f1d + g * 4 + 2);
                    ulonglong2 w1  = __ldg((const ulonglong2*)(g_WcatT + g * NROWS + r0));
                    MM8(p1, f01, f23, w1);
                    ulonglong2 c01 = *(const ulonglong2*)(cfd + g * 4);
                    ulonglong2 c23 = *(const ulonglong2*)(cfd + g * 4 + 2);
                    ulonglong2 w2  = __ldg((const ulonglong2*)(g_WcatT + (32 + g) * NROWS + r0));
                    MM8(p2, c01, c23, w2);
                }
            }
        }

        // ---- grid exchange: warp 7 polls counter, reduces partials -> S ----
        if (t > 0 && (tid >> 5) == 7) {
            const int lane = tid & 31;
            if (lane == 0) {
                unsigned target = (unsigned)NCTA * (unsigned)t;
                while (*((volatile unsigned*)&g_arrive) < target) { }
            }
            __syncwarp();
            __threadfence();
            float p = *((volatile float*)&g_partials[t & 1][lane])
                    + *((volatile float*)&g_partials[t & 1][lane + 32])
                    + *((volatile float*)&g_partials[t & 1][lane + 64])
                    + *((volatile float*)&g_partials[t & 1][lane + 96]);
            p = wsum32(p);
            if (lane == 0) misc[4] = p;
        }
        __syncthreads();   // sync2: S available
        const float invS = 1.0f / (misc[4] + 1e-5f);

        // ---- combine + activations -> smem ----
#pragma unroll
        for (int it = 0; it < 2; ++it) {
            if (it == 1 && tid >= 40) break;
            const int r0 = (tid + it * NTHREADS) * 4;
#pragma unroll
            for (int b = 0; b < 4; ++b) {
#pragma unroll
                for (int jp = 0; jp < 2; ++jp) {
                    float2 v1 = unp(a1[it][b * 2 + jp]);
                    float2 v2 = unp(a2[it][b * 2 + jp]);
                    float p0 = fmaf(invS, v2.x, v1.x) + bc_s[r0 + jp * 2 + 0];
                    float p1 = fmaf(invS, v2.y, v1.y) + bc_s[r0 + jp * 2 + 1];
                    if (r0 < 128) {
                        gi_s[b * 128 + r0 + jp * 2 + 0] = sigm(p0);
                        gi_s[b * 128 + r0 + jp * 2 + 1] = sigm(p1);
                    } else if (r0 < 1152) {
                        rr_s[b * 1024 + (r0 - 128) + jp * 2 + 0] = fmaxf(p0, 0.0f);
                        rr_s[b * 1024 + (r0 - 128) + jp * 2 + 1] = fmaxf(p1, 0.0f);
                    } else {
                        o_s[b * 32 + (r0 - 1152) + jp * 2 + 0] = sigm(p0);
                        o_s[b * 32 + (r0 - 1152) + jp * 2 + 1] = sigm(p1);
                    }
                }
            }
        }
        // tanh of MR pre-activation (uses invS and local q)
        th_s[bq * 64 + gq] = tanhf(fmaf(invS, q, -d0_s[gq]));
        __syncthreads();   // sync3: activations + th ready

        // ---- parallel epilogue part 1: coefs (warps 0-3) | MR-LN (warps 4-7) ----
        if (tid < 128) {
            int b = tid >> 5, n = tid & 31;
            float s = 0.0f;
#pragma unroll
            for (int p = 0; p < 32; p += 4) {
                float4 v = *(const float4*)&rr_s[b * 1024 + n * 32 + p];
                s += v.x + v.y + v.z + v.w;
            }
            coef_r[tid] = c_s[b * 32 + n] / fmaxf(s, 1e-12f);
            if (tid < 16) {
                int b2 = tid >> 2, ii = tid & 3;
                float si = 0.0f;
#pragma unroll
                for (int p = 0; p < 32; ++p) si += gi_s[b2 * 128 + ii * 32 + p];
                coef_i[tid] = xm_s[tid] / fmaxf(si, 1e-12f);
            }
        } else {
            int b = (tid - 128) >> 5, o = tid & 31;
            float pre = 0.0f;
#pragma unroll
            for (int g = 0; g < 64; ++g) pre += th_s[b * 64 + g] * sWr_s[g * 32 + o];
            float mu = wsum32(pre) * (1.0f / 32.0f);
            float d = pre - mu;
            float var = wsum32(d * d) * (1.0f / 32.0f);
            ov1_s[b * 32 + o] = d * rsqrtf(var + 1e-5f) * lng_s[o] + lnb_s[o];
        }
        __syncthreads();   // sync4

        // ---- final: m, MR gate, outputs, carry update ----
        if (tid < 128) {
            int b = tid >> 5, o = tid & 31;
            float m = 0.0f;
#pragma unroll
            for (int ii = 0; ii < 4; ++ii) m += coef_i[b * 4 + ii] * gi_s[b * 128 + ii * 32 + o];
#pragma unroll
            for (int n = 0; n < 32; ++n)  m += coef_r[b * 32 + n] * rr_s[b * 1024 + n * 32 + o];

            float og  = o_s[b * 32 + o];
            float ov1 = ov1_s[b * 32 + o];
            float f = 1.0f - og;
            float ov2 = ov1 - fmaxf(ov1 - f, 0.0f);
            float MR = fmaxf(ov2 + 1.0f - f, 0.0f) + f - 1.0f;
            float opr = og + MR;
            float h = og * m;
            float cnew = (1.0f - opr) * m;
            float mrf = MR * m;

            size_t base = ((size_t)t * BATCH + (bbase + b)) * OUT_DIM + o;
            out[base]               = h;
            out[OSTRIDE + base]     = cnew;
            out[2 * OSTRIDE + base] = og;
            out[3 * OSTRIDE + base] = MR;
            out[4 * OSTRIDE + base] = opr;
            out[5 * OSTRIDE + base] = mrf;
            out[6 * OSTRIDE + base] = h;

            c_s[b * 32 + o] = cnew;
            cfd[o * 4 + b] = dup2(cnew);
            float a = wsum32(fabsf(cnew));
            if (o == 0) misc[b] = a;
        }
        __syncthreads();   // sync5: carry + misc ready

        if (t < T_STEPS - 1 && tid == 0) {
            float part = misc[0] + misc[1] + misc[2] + misc[3];
            *((volatile float*)&g_partials[(t + 1) & 1][cta]) = part;
            __threadfence();
            atomicAdd(&g_arrive, 1u);
        }
        xcur = xnext;
    }
}

// ---------------- launch ----------------
extern "C" void kernel_launch(void* const* d_in, const int* in_sizes, int n_in,
                              void* d_out, int out_size)
{
    const float* xm   = (const float*)d_in[0];
    const float* xa   = (const float*)d_in[1];
    const float* W_i  = (const float*)d_in[2];
    const float* b_i  = (const float*)d_in[3];
    const float* W_r  = (const float*)d_in[4];
    const float* b_r  = (const float*)d_in[5];
    const float* W_o  = (const float*)d_in[6];
    const float* b_o  = (const float*)d_in[7];
    const float* W_s  = (const float*)d_in[8];
    const float* W_rm = (const float*)d_in[9];
    const float* b0   = (const float*)d_in[10];
    const float* lng  = (const float*)d_in[11];
    const float* lnb  = (const float*)d_in[12];
    float* out = (float*)d_out;

    cudaFuncSetAttribute(mclstm_kernel, cudaFuncAttributeMaxDynamicSharedMemorySize, SMEM_BYTES);

    prep_kernel<<<320, 256>>>(W_i, b_i, W_r, b_r, W_o, b_o, W_s, W_rm, b0);
    mclstm_kernel<<<NCTA, NTHREADS, SMEM_BYTES>>>(xm, xa, lng, lnb, out);
}

// round 3
// speedup vs baseline: 1.3782x; 1.0536x over previous
#include <cuda_runtime.h>
#include <math.h>

#define T_STEPS 512
#define BATCH   512
#define IN_DIM  4
#define AUX_DIM 28
#define OUT_DIM 32
#define G_DIM   64
#define NROWS   1184      // 128 (W_i) + 1024 (W_r) + 32 (W_o)
#define NCTA    128
#define NTHREADS 512
#define R_SM    640       // Wcat rows cached in smem (warps 0-4 exactly)

typedef unsigned long long ull;

// ---------------- device globals ----------------
__device__ float g_WcatT[G_DIM * NROWS];   // [g][row]
__device__ float g_bcat[NROWS];
__device__ float g_E[OUT_DIM * G_DIM];     // exp(W_s)        [o][g]
__device__ float g_sWr[G_DIM * OUT_DIM];   // sigmoid(W_rm.T) [g][o]
__device__ float g_d0[G_DIM];              // b0 @ exp(W_s)   [g]
__device__ ull   g_msg[2][NCTA];           // (tag<<32)|float partial, per CTA

__device__ __forceinline__ float sigm(float x) {
    return __fdividef(1.0f, 1.0f + __expf(-x));
}
__device__ __forceinline__ float tanh_fast(float x) {
    x = fminf(fmaxf(x, -12.0f), 12.0f);
    float e = __expf(2.0f * x);
    return __fdividef(e - 1.0f, e + 1.0f);
}
__device__ __forceinline__ float wsum32(float v) {
#pragma unroll
    for (int s = 16; s > 0; s >>= 1) v += __shfl_xor_sync(0xffffffffu, v, s);
    return v;
}
__device__ __forceinline__ void ffma2(ull& d, ull a, ull b) {
    asm("fma.rn.f32x2 %0, %1, %2, %0;" : "+l"(d) : "l"(a), "l"(b));
}
__device__ __forceinline__ ull dup2(float x) {
    ull r; asm("mov.b64 %0, {%1, %1};" : "=l"(r) : "f"(x)); return r;
}
__device__ __forceinline__ float2 unp(ull v) {
    float2 r;
    r.x = __uint_as_float((unsigned)v);
    r.y = __uint_as_float((unsigned)(v >> 32));
    return r;
}

#define MM8(ACC, F01, F23, W) \
    ffma2(ACC[0], F01.x, W.x); ffma2(ACC[1], F01.x, W.y); \
    ffma2(ACC[2], F01.y, W.x); ffma2(ACC[3], F01.y, W.y); \
    ffma2(ACC[4], F23.x, W.x); ffma2(ACC[5], F23.x, W.y); \
    ffma2(ACC[6], F23.y, W.x); ffma2(ACC[7], F23.y, W.y);

// ---------------- prep: pack weights, derived constants, reset sync ----------------
__global__ void prep_kernel(const float* __restrict__ W_i, const float* __restrict__ b_i,
                            const float* __restrict__ W_r, const float* __restrict__ b_r,
                            const float* __restrict__ W_o, const float* __restrict__ b_o,
                            const float* __restrict__ W_s, const float* __restrict__ W_rm,
                            const float* __restrict__ b0)
{
    int idx = blockIdx.x * blockDim.x + threadIdx.x;
    if (idx < G_DIM * NROWS) {
        int g = idx / NROWS, r = idx % NROWS;
        float v;
        if (r < 128)        v = W_i[r * G_DIM + g];
        else if (r < 1152)  v = W_r[(r - 128) * G_DIM + g];
        else                v = W_o[(r - 1152) * G_DIM + g];
        g_WcatT[idx] = v;
    }
    int i2 = idx - G_DIM * NROWS;
    if (i2 >= 0 && i2 < NROWS)
        g_bcat[i2] = (i2 < 128) ? b_i[i2] : (i2 < 1152) ? b_r[i2 - 128] : b_o[i2 - 1152];
    int i3 = i2 - NROWS;
    if (i3 >= 0 && i3 < OUT_DIM * G_DIM) g_E[i3] = expf(W_s[i3]);
    int i4 = i3 - OUT_DIM * G_DIM;
    if (i4 >= 0 && i4 < G_DIM * OUT_DIM) {
        int g = i4 / OUT_DIM, o = i4 % OUT_DIM;
        g_sWr[i4] = 1.0f / (1.0f + expf(-W_rm[o * G_DIM + g]));
    }
    int i5 = i4 - G_DIM * OUT_DIM;
    if (i5 >= 0 && i5 < G_DIM) {
        float a = 0.0f;
        for (int o = 0; o < OUT_DIM; ++o) a += b0[o] * expf(W_s[o * G_DIM + i5]);
        g_d0[i5] = a;
    }
    int i6 = i5 - G_DIM;
    if (i6 >= 0 && i6 < 2 * NCTA) ((ull*)g_msg)[i6] = 0ull;
}

// ---------------- smem layout (float offsets) ----------------
#define OFF_WS    0
#define OFF_E     (OFF_WS + G_DIM * R_SM)         // 40960
#define OFF_SWR   (OFF_E + 2048)                  // 43008
#define OFF_BC    (OFF_SWR + 2048)                // 45056 (1184)
#define OFF_F1D   (OFF_BC + 1184)                 // 46240 (ull[32*4])
#define OFF_CFD   (OFF_F1D + 256)                 // 46496 (ull[32*4])
#define OFF_GI    (OFF_CFD + 256)                 // 46752 [4][128]
#define OFF_RR    (OFF_GI + 512)                  // 47264 [4][1024]
#define OFF_OS    (OFF_RR + 4096)                 // 51360 [4][32]
#define OFF_C     (OFF_OS + 128)                  // 51488 [4][32]
#define OFF_XM    (OFF_C + 128)                   // 51616 [4][4]
#define OFF_CR    (OFF_XM + 16)                   // 51632 [4][32]
#define OFF_CI    (OFF_CR + 128)                  // 51760 [4][4]
#define OFF_TH    (OFF_CI + 16)                   // 51776 [4][64]
#define OFF_D0    (OFF_TH + 256)                  // 52032 [64]
#define OFF_OV1   (OFF_D0 + 64)                   // 52096 [4][32]
#define OFF_LNG   (OFF_OV1 + 128)                 // 52224
#define OFF_LNB   (OFF_LNG + 32)                  // 52256
#define OFF_QS    (OFF_LNB + 32)                  // 52288 [4][64] q = c @ E
#define OFF_MISC  (OFF_QS + 256)                  // 52544 [8]; [0..3]=|c| rows, [4]=S
#define SMEM_FLOATS (OFF_MISC + 8)
#define SMEM_BYTES  (SMEM_FLOATS * 4)             // ~205.3 KB

__global__ void __launch_bounds__(NTHREADS, 1)
mclstm_kernel(const float* __restrict__ xm, const float* __restrict__ xa,
              const float* __restrict__ ln_g, const float* __restrict__ ln_b,
              float* __restrict__ out)
{
    extern __shared__ float sm[];
    float* Ws     = sm + OFF_WS;
    float* E_s    = sm + OFF_E;
    float* sWr_s  = sm + OFF_SWR;
    float* bc_s   = sm + OFF_BC;
    ull*   f1d    = (ull*)(sm + OFF_F1D);
    ull*   cfd    = (ull*)(sm + OFF_CFD);
    float* gi_s   = sm + OFF_GI;
    float* rr_s   = sm + OFF_RR;
    float* o_s    = sm + OFF_OS;
    float* c_s    = sm + OFF_C;
    float* xm_s   = sm + OFF_XM;
    float* coef_r = sm + OFF_CR;
    float* coef_i = sm + OFF_CI;
    float* th_s   = sm + OFF_TH;
    float* d0_s   = sm + OFF_D0;
    float* ov1_s  = sm + OFF_OV1;
    float* lng_s  = sm + OFF_LNG;
    float* lnb_s  = sm + OFF_LNB;
    float* qs     = sm + OFF_QS;
    float* misc   = sm + OFF_MISC;

    const int tid = threadIdx.x;
    const int cta = blockIdx.x;
    const int bbase = cta * 4;
    const size_t OSTRIDE = (size_t)T_STEPS * BATCH * OUT_DIM;

    // input-feeder threads: 256..383, mapping (pb, pg)
    const bool feeder = (tid >= 256 && tid < 384);
    int pb = 0, pg = 0;
    float xnext = 0.0f;
    if (feeder) {
        int idx = tid - 256;
        pb = idx >> 5; pg = idx & 31;
        xnext = (pg < IN_DIM) ? xm[(size_t)(bbase + pb) * IN_DIM + pg]
                              : xa[(size_t)(bbase + pb) * AUX_DIM + (pg - IN_DIM)];
    }

    // ---- one-time smem fills ----
    for (int i = tid; i < G_DIM * R_SM; i += NTHREADS) {
        int g = i / R_SM, r = i - g * R_SM;
        Ws[i] = g_WcatT[g * NROWS + r];
    }
    for (int i = tid; i < 2048; i += NTHREADS) { E_s[i] = g_E[i]; sWr_s[i] = g_sWr[i]; }
    for (int i = tid; i < NROWS; i += NTHREADS) bc_s[i] = g_bcat[i];
    if (tid < G_DIM) d0_s[tid] = g_d0[tid];
    if (tid < OUT_DIM) { lng_s[tid] = ln_g[tid]; lnb_s[tid] = ln_b[tid]; }
    if (tid < 128) { c_s[tid] = 0.0f; cfd[tid] = 0ull; }
    for (int i = tid; i < 256; i += NTHREADS) qs[i] = 0.0f;
    if (tid < 8) misc[tid] = 0.0f;
    if (feeder) {
        f1d[pg * 4 + pb] = dup2(xnext);
        if (pg < IN_DIM) xm_s[pb * 4 + pg] = xnext;
    }

    for (int t = 0; t < T_STEPS; ++t) {
        __syncthreads();   // sync A: carry state (qs, cfd, c_s, misc, f1d) ready

        // ---- publish |c| partial (from previous step) ----
        if (t > 0 && tid == 0) {
            float part = (misc[0] + misc[1]) + (misc[2] + misc[3]);
            ull msg = ((ull)(unsigned)t << 32) | (ull)__float_as_uint(part);
            *((volatile ull*)&g_msg[t & 1][cta]) = msg;
        }
        // ---- poller warp 15: gather all 128 partials -> S (overlaps GEMM) ----
        if (t > 0 && tid >= 480) {
            const int lane = tid & 31;
            float p = 0.0f;
#pragma unroll
            for (int k = 0; k < 4; ++k) {
                volatile ull* slot = &g_msg[t & 1][lane + 32 * k];
                ull m;
                do { m = *slot; } while ((unsigned)(m >> 32) != (unsigned)t);
                p += __uint_as_float((unsigned)m);
            }
            p = wsum32(p);
            if (lane == 0) misc[4] = p;
        }
        // ---- feeders prefetch next-step inputs (idle during GEMM) ----
        if (feeder && t + 1 < T_STEPS) {
            xnext = (pg < IN_DIM)
                ? xm[((size_t)(t + 1) * BATCH + bbase + pb) * IN_DIM + pg]
                : xa[((size_t)(t + 1) * BATCH + bbase + pb) * AUX_DIM + (pg - IN_DIM)];
        }

        // ---- GEMM: x-half (f1d) and c-half (cfd, un-normalized) ----
        ull a1[8], a2[8];
        if (tid < NROWS / 4) {
#pragma unroll
            for (int k = 0; k < 8; ++k) { a1[k] = 0ull; a2[k] = 0ull; }
            const int r0 = tid * 4;
            if (tid < R_SM / 4) {
#pragma unroll 8
                for (int g = 0; g < 32; ++g) {
                    ulonglong2 f01 = *(const ulonglong2*)(f1d + g * 4);
                    ulonglong2 f23 = *(const ulonglong2*)(f1d + g * 4 + 2);
                    ulonglong2 w1  = *(const ulonglong2*)(Ws + g * R_SM + r0);
                    MM8(a1, f01, f23, w1);
                    ulonglong2 c01 = *(const ulonglong2*)(cfd + g * 4);
                    ulonglong2 c23 = *(const ulonglong2*)(cfd + g * 4 + 2);
                    ulonglong2 w2  = *(const ulonglong2*)(Ws + (32 + g) * R_SM + r0);
                    MM8(a2, c01, c23, w2);
                }
            } else {
#pragma unroll 8
                for (int g = 0; g < 32; ++g) {
                    ulonglong2 f01 = *(const ulonglong2*)(f1d + g * 4);
                    ulonglong2 f23 = *(const ulonglong2*)(f1d + g * 4 + 2);
                    ulonglong2 w1  = __ldg((const ulonglong2*)(g_WcatT + g * NROWS + r0));
                    MM8(a1, f01, f23, w1);
                    ulonglong2 c01 = *(const ulonglong2*)(cfd + g * 4);
                    ulonglong2 c23 = *(const ulonglong2*)(cfd + g * 4 + 2);
                    ulonglong2 w2  = __ldg((const ulonglong2*)(g_WcatT + (32 + g) * NROWS + r0));
                    MM8(a2, c01, c23, w2);
                }
            }
        }
        __syncthreads();   // sync B: misc[4] (S) visible; GEMM accs in regs
        const float invS = __fdividef(1.0f, misc[4] + 1e-5f);

        // ---- combine + activations ----
        if (tid < NROWS / 4) {
            const int r0 = tid * 4;
            float4 bb = *(const float4*)&bc_s[r0];
            const float bias[4] = { bb.x, bb.y, bb.z, bb.w };
#pragma unroll
            for (int b = 0; b < 4; ++b) {
#pragma unroll
                for (int jp = 0; jp < 2; ++jp) {
                    float2 v1 = unp(a1[b * 2 + jp]);
                    float2 v2 = unp(a2[b * 2 + jp]);
                    float p0 = fmaf(invS, v2.x, v1.x) + bias[jp * 2 + 0];
                    float p1 = fmaf(invS, v2.y, v1.y) + bias[jp * 2 + 1];
                    if (r0 < 128) {
                        gi_s[b * 128 + r0 + jp * 2 + 0] = sigm(p0);
                        gi_s[b * 128 + r0 + jp * 2 + 1] = sigm(p1);
                    } else if (r0 < 1152) {
                        rr_s[b * 1024 + (r0 - 128) + jp * 2 + 0] = fmaxf(p0, 0.0f);
                        rr_s[b * 1024 + (r0 - 128) + jp * 2 + 1] = fmaxf(p1, 0.0f);
                    } else {
                        o_s[b * 32 + (r0 - 1152) + jp * 2 + 0] = sigm(p0);
                        o_s[b * 32 + (r0 - 1152) + jp * 2 + 1] = sigm(p1);
                    }
                }
            }
        }
        if (tid < 256)   // th = tanh(invS*q - d0)
            th_s[tid] = tanh_fast(fmaf(invS, qs[tid], -d0_s[tid & 63]));
        __syncthreads();   // sync C

        // ---- parallel: coef_r (0-255) | LN (256-383) | coef_i (384-399) ----
        if (tid < 256) {
            int pair = tid >> 1, half = tid & 1;
            int b = pair >> 5, n = pair & 31;
            const float* row = rr_s + b * 1024 + n * 32 + half * 16;
            float4 v0 = *(const float4*)(row);
            float4 v1 = *(const float4*)(row + 4);
            float4 v2 = *(const float4*)(row + 8);
            float4 v3 = *(const float4*)(row + 12);
            float s = ((v0.x + v0.y) + (v0.z + v0.w)) + ((v1.x + v1.y) + (v1.z + v1.w))
                    + ((v2.x + v2.y) + (v2.z + v2.w)) + ((v3.x + v3.y) + (v3.z + v3.w));
            s += __shfl_xor_sync(0xffffffffu, s, 1);
            if (!half) coef_r[pair] = __fdividef(c_s[b * 32 + n], fmaxf(s, 1e-12f));
        } else if (tid < 384) {
            int idx = tid - 256, b = idx >> 5, o = idx & 31;
            const float* thb = th_s + b * 64;
            float p0 = 0.f, p1 = 0.f, p2 = 0.f, p3 = 0.f;
#pragma unroll
            for (int g = 0; g < 64; g += 4) {
                p0 = fmaf(thb[g],     sWr_s[g * 32 + o],       p0);
                p1 = fmaf(thb[g + 1], sWr_s[(g + 1) * 32 + o], p1);
                p2 = fmaf(thb[g + 2], sWr_s[(g + 2) * 32 + o], p2);
                p3 = fmaf(thb[g + 3], sWr_s[(g + 3) * 32 + o], p3);
            }
            float pre = (p0 + p1) + (p2 + p3);
            float s1 = pre, s2 = pre * pre;
#pragma unroll
            for (int sft = 16; sft > 0; sft >>= 1) {
                s1 += __shfl_xor_sync(0xffffffffu, s1, sft);
                s2 += __shfl_xor_sync(0xffffffffu, s2, sft);
            }
            float mu  = s1 * (1.0f / 32.0f);
            float var = fmaxf(s2 * (1.0f / 32.0f) - mu * mu, 0.0f);
            ov1_s[idx] = (pre - mu) * rsqrtf(var + 1e-5f) * lng_s[o] + lnb_s[o];
        } else if (tid < 400) {
            int idx = tid - 384, b2 = idx >> 2, ii = idx & 3;
            const float* gb = gi_s + b2 * 128 + ii * 32;
            float s0 = 0.f, s1 = 0.f, s2 = 0.f, s3 = 0.f;
#pragma unroll
            for (int p = 0; p < 32; p += 4) {
                s0 += gb[p]; s1 += gb[p + 1]; s2 += gb[p + 2]; s3 += gb[p + 3];
            }
            float si = (s0 + s1) + (s2 + s3);
            coef_i[idx] = __fdividef(xm_s[idx], fmaxf(si, 1e-12f));
        }
        __syncthreads();   // sync D

        // ---- final: m, MR gate, outputs, carry + next-step derived state ----
        if (tid < 128) {
            int b = tid >> 5, o = tid & 31;
            float m0, m1, m2 = 0.f, m3 = 0.f;
            m0 = coef_i[b * 4 + 0] * gi_s[b * 128 + o]
               + coef_i[b * 4 + 1] * gi_s[b * 128 + 32 + o];
            m1 = coef_i[b * 4 + 2] * gi_s[b * 128 + 64 + o]
               + coef_i[b * 4 + 3] * gi_s[b * 128 + 96 + o];
#pragma unroll
            for (int n = 0; n < 32; n += 4) {
                m0 = fmaf(coef_r[b * 32 + n],     rr_s[b * 1024 + n * 32 + o],       m0);
                m1 = fmaf(coef_r[b * 32 + n + 1], rr_s[b * 1024 + (n + 1) * 32 + o], m1);
                m2 = fmaf(coef_r[b * 32 + n + 2], rr_s[b * 1024 + (n + 2) * 32 + o], m2);
                m3 = fmaf(coef_r[b * 32 + n + 3], rr_s[b * 1024 + (n + 3) * 32 + o], m3);
            }
            float m = (m0 + m1) + (m2 + m3);

            float og  = o_s[b * 32 + o];
            float ov1 = ov1_s[b * 32 + o];
            float f = 1.0f - og;
            float ov2 = ov1 - fmaxf(ov1 - f, 0.0f);
            float MR = fmaxf(ov2 + 1.0f - f, 0.0f) + f - 1.0f;
            float opr = og + MR;
            float h = og * m;
            float cnew = (1.0f - opr) * m;
            float mrf = MR * m;

            size_t base = ((size_t)t * BATCH + (bbase + b)) * OUT_DIM + o;
            out[base]               = h;
            out[OSTRIDE + base]     = cnew;
            out[2 * OSTRIDE + base] = og;
            out[3 * OSTRIDE + base] = MR;
            out[4 * OSTRIDE + base] = opr;
            out[5 * OSTRIDE + base] = mrf;
            out[6 * OSTRIDE + base] = h;

            c_s[b * 32 + o] = cnew;
            cfd[o * 4 + b]  = dup2(cnew);
            float a = wsum32(fabsf(cnew));
            if (o == 0) misc[b] = a;

            // next-step q = c_new @ E via in-warp shuffle (warp == batch row)
            float qa = 0.f, qb = 0.f;
#pragma unroll
            for (int o2 = 0; o2 < 32; ++o2) {
                float cv = __shfl_sync(0xffffffffu, cnew, o2);
                qa = fmaf(cv, E_s[o2 * 64 + o],      qa);
                qb = fmaf(cv, E_s[o2 * 64 + 32 + o], qb);
            }
            qs[b * 64 + o]      = qa;
            qs[b * 64 + 32 + o] = qb;
        } else if (feeder && t + 1 < T_STEPS) {
            // next-step feat (x part)
            f1d[pg * 4 + pb] = dup2(xnext);
            if (pg < IN_DIM) xm_s[pb * 4 + pg] = xnext;
        }
    }
}

// ---------------- launch ----------------
extern "C" void kernel_launch(void* const* d_in, const int* in_sizes, int n_in,
                              void* d_out, int out_size)
{
    const float* xm   = (const float*)d_in[0];
    const float* xa   = (const float*)d_in[1];
    const float* W_i  = (const float*)d_in[2];
    const float* b_i  = (const float*)d_in[3];
    const float* W_r  = (const float*)d_in[4];
    const float* b_r  = (const float*)d_in[5];
    const float* W_o  = (const float*)d_in[6];
    const float* b_o  = (const float*)d_in[7];
    const float* W_s  = (const float*)d_in[8];
    const float* W_rm = (const float*)d_in[9];
    const float* b0   = (const float*)d_in[10];
    const float* lng  = (const float*)d_in[11];
    const float* lnb  = (const float*)d_in[12];
    float* out = (float*)d_out;

    cudaFuncSetAttribute(mclstm_kernel, cudaFuncAttributeMaxDynamicSharedMemorySize, SMEM_BYTES);

    prep_kernel<<<320, 256>>>(W_i, b_i, W_r, b_r, W_o, b_o, W_s, W_rm, b0);
    mclstm_kernel<<<NCTA, NTHREADS, SMEM_BYTES>>>(xm, xa, lng, lnb, out);
}